// round 10
// baseline (speedup 1.0000x reference)
#include <cuda_runtime.h>
#include <math.h>

#define S_ 32
#define H_ 768
#define I_ 768
#define E_ 32
#define TOPK_ 4
#define LIMIT_ 7.0f
#define ALPHA_ 1.702f
#define EPS_ 1e-5f

#define TB 4           // tokens per work chunk
#define MAXW 64        // max work chunks
#define NCH 6          // weight column-chunks (768/128)

// Scratch (device globals: allocation-free)
__device__ float g_t[S_ * H_];           // rmsnormed tokens
__device__ int   g_idx[S_ * TOPK_];      // top-k expert ids
__device__ float g_wts[S_ * TOPK_];      // softmax weights
__device__ int   g_cnt[E_];              // tokens per expert
__device__ int   g_sel[E_ * S_];         // sel = s*4+k per expert slot
__device__ float g_act[S_ * TOPK_ * I_]; // post-SwiGLU activations
__device__ int   g_work[MAXW * 3];       // (expert, base, len)
__device__ int   g_nw;

// ---- mbarrier + bulk-copy helpers ------------------------------------------
__device__ __forceinline__ unsigned smem_u32(const void* p)
{
    return (unsigned)__cvta_generic_to_shared(p);
}
__device__ __forceinline__ void mbar_init(unsigned a, unsigned cnt)
{
    asm volatile("mbarrier.init.shared.b64 [%0], %1;" :: "r"(a), "r"(cnt) : "memory");
}
__device__ __forceinline__ void mbar_expect_tx(unsigned a, unsigned bytes)
{
    asm volatile("mbarrier.arrive.expect_tx.shared.b64 _, [%0], %1;"
                 :: "r"(a), "r"(bytes) : "memory");
}
__device__ __forceinline__ void mbar_wait(unsigned a, unsigned ph)
{
    asm volatile(
        "{\n\t"
        ".reg .pred P;\n\t"
        "WL_%=:\n\t"
        "mbarrier.try_wait.parity.acquire.cta.shared::cta.b64 P, [%0], %1, 0x989680;\n\t"
        "@P bra WD_%=;\n\t"
        "bra WL_%=;\n\t"
        "WD_%=:\n\t"
        "}"
        :: "r"(a), "r"(ph) : "memory");
}
__device__ __forceinline__ void bulk512(unsigned dst, const void* src, unsigned mbar)
{
    asm volatile(
        "cp.async.bulk.shared::cta.global.mbarrier::complete_tx::bytes [%0], [%1], 512, [%2];"
        :: "r"(dst), "l"(src), "r"(mbar) : "memory");
}

// issue one 32-row x 128-col chunk (16 KB) as 32 bulk copies. Single thread.
__device__ __forceinline__ void issue_chunk_bulk(
    float* wbuf, const float* wbase, int c, unsigned mbar)
{
    unsigned dst = smem_u32(wbuf);
    const char* src = (const char*)(wbase + c * 128);
#pragma unroll
    for (int r = 0; r < 32; r++)
        bulk512(dst + r * 512, src + (size_t)r * (H_ * 4), mbar);
}

// Packed reduction: 4 per-thread partials -> lane L (L<4) holds full sum of a[L].
__device__ __forceinline__ float reduce4(float a0, float a1, float a2, float a3, int lane)
{
    float w0 = (lane & 1) ? a1 : a0;
    float o0 = (lane & 1) ? a0 : a1;
    float b0 = w0 + __shfl_xor_sync(0xffffffffu, o0, 1);
    float w1 = (lane & 1) ? a3 : a2;
    float o1 = (lane & 1) ? a2 : a3;
    float b1 = w1 + __shfl_xor_sync(0xffffffffu, o1, 1);
    float w2 = (lane & 2) ? b1 : b0;
    float o2 = (lane & 2) ? b0 : b1;
    float c  = w2 + __shfl_xor_sync(0xffffffffu, o2, 2);
    c += __shfl_xor_sync(0xffffffffu, c, 4);
    c += __shfl_xor_sync(0xffffffffu, c, 8);
    c += __shfl_xor_sync(0xffffffffu, c, 16);
    return c;
}

// compute one chunk: this warp's 4 rows x 4 tokens
__device__ __forceinline__ void chunk_fma(
    const float* wbuf, const float* tile, int c, int wid, int lane, float acc[4][4])
{
    const float4* ws = (const float4*)wbuf + (size_t)(wid * 4) * 32 + lane;
    const float4* ts = (const float4*)tile + c * 32 + lane;
    float4 w0 = ws[0], w1 = ws[32], w2 = ws[64], w3 = ws[96];
    float4 t0 = ts[0], t1 = ts[192], t2 = ts[384], t3 = ts[576];

#define FMA4(r, wv, i, tv) \
    acc[r][i] += wv.x * tv.x + wv.y * tv.y + wv.z * tv.z + wv.w * tv.w;
    FMA4(0, w0, 0, t0) FMA4(0, w0, 1, t1) FMA4(0, w0, 2, t2) FMA4(0, w0, 3, t3)
    FMA4(1, w1, 0, t0) FMA4(1, w1, 1, t1) FMA4(1, w1, 2, t2) FMA4(1, w1, 3, t3)
    FMA4(2, w2, 0, t0) FMA4(2, w2, 1, t1) FMA4(2, w2, 2, t2) FMA4(2, w2, 3, t3)
    FMA4(3, w3, 0, t0) FMA4(3, w3, 1, t1) FMA4(3, w3, 2, t2) FMA4(3, w3, 3, t3)
#undef FMA4
}

// ---------------------------------------------------------------------------
// Kernel 1: RMSNorm + router (logits, top-4, softmax) + residual init
// ---------------------------------------------------------------------------
__global__ void __launch_bounds__(256) k_norm_router(
    const float* __restrict__ x, const float* __restrict__ nscale,
    const float* __restrict__ gw, const float* __restrict__ gb,
    float* __restrict__ out)
{
    int s   = blockIdx.x;
    int tid = threadIdx.x;
    int lane = tid & 31, wid = tid >> 5;

    __shared__ float sh_t[H_];
    __shared__ float red[8];
    __shared__ float logits[E_];

    float v0[3];
    float ss = 0.f;
#pragma unroll
    for (int q = 0; q < 3; q++) {
        float v = x[s * H_ + tid + 256 * q];
        v0[q] = v;
        ss += v * v;
    }
#pragma unroll
    for (int o = 16; o; o >>= 1) ss += __shfl_xor_sync(0xffffffffu, ss, o);
    if (lane == 0) red[wid] = ss;
    __syncthreads();
    if (tid < 8) {
        float r = red[tid];
#pragma unroll
        for (int o = 4; o; o >>= 1) r += __shfl_xor_sync(0xffu, r, o);
        if (tid == 0) red[0] = r;
    }
    __syncthreads();
    float rms = rsqrtf(red[0] / (float)H_ + EPS_);

#pragma unroll
    for (int q = 0; q < 3; q++) {
        int j = tid + 256 * q;
        float t = v0[q] * rms * nscale[j];
        sh_t[j] = t;
        g_t[s * H_ + j] = t;
        out[s * H_ + j] = v0[q];   // residual init out = x
    }
    __syncthreads();

#pragma unroll
    for (int e4 = 0; e4 < 4; e4++) {
        int e = wid * 4 + e4;
        float acc = 0.f;
        for (int j = lane; j < H_; j += 32) acc += sh_t[j] * gw[e * H_ + j];
#pragma unroll
        for (int o = 16; o; o >>= 1) acc += __shfl_xor_sync(0xffffffffu, acc, o);
        if (lane == 0) logits[e] = acc + gb[e];
    }
    __syncthreads();

    if (tid == 0) {
        float l[E_];
#pragma unroll
        for (int e = 0; e < E_; e++) l[e] = logits[e];
        float vals[TOPK_];
        int   ids[TOPK_];
#pragma unroll
        for (int k = 0; k < TOPK_; k++) {
            float m = -1e30f; int mi = 0;
            for (int e = 0; e < E_; e++) {
                if (l[e] > m) { m = l[e]; mi = e; }
            }
            vals[k] = m; ids[k] = mi; l[mi] = -1e30f;
        }
        float mx = vals[0], sum = 0.f, w[TOPK_];
#pragma unroll
        for (int k = 0; k < TOPK_; k++) { w[k] = __expf(vals[k] - mx); sum += w[k]; }
        float inv = 1.f / sum;
#pragma unroll
        for (int k = 0; k < TOPK_; k++) {
            g_idx[s * TOPK_ + k] = ids[k];
            g_wts[s * TOPK_ + k] = w[k] * inv;
        }
    }
}

// ---------------------------------------------------------------------------
// Kernel 2: build per-expert selection lists + work chunks (single thread)
// ---------------------------------------------------------------------------
__global__ void k_build()
{
    if (threadIdx.x == 0 && blockIdx.x == 0) {
        for (int e = 0; e < E_; e++) g_cnt[e] = 0;
        for (int sel = 0; sel < S_ * TOPK_; sel++) {
            int e = g_idx[sel];
            g_sel[e * S_ + g_cnt[e]] = sel;
            g_cnt[e]++;
        }
        int w = 0;
        for (int e = 0; e < E_; e++) {
            int n = g_cnt[e];
            for (int base = 0; base < n; base += TB) {
                int len = n - base; if (len > TB) len = TB;
                g_work[w * 3 + 0] = e;
                g_work[w * 3 + 1] = base;
                g_work[w * 3 + 2] = len;
                w++;
            }
        }
        g_nw = w;
    }
}

// ---------------------------------------------------------------------------
// Kernel 3: expert MLP-1 (32 w1 rows/block), bulk-copy 2-stage pipeline,
//           SwiGLU fused in registers.
// grid (2I_/32, MAXW), 256 threads
// ---------------------------------------------------------------------------
__global__ void __launch_bounds__(256, 4) k_mlp1(
    const float* __restrict__ w1, const float* __restrict__ b1)
{
    int widx = blockIdx.y;
    if (widx >= g_nw) return;
    int e    = g_work[widx * 3 + 0];
    int base = g_work[widx * 3 + 1];
    int n    = g_work[widx * 3 + 2];

    __shared__ float tile[TB * H_];               // 12 KB token tile
    __shared__ float wbuf[2][32 * 128];           // 2 x 16 KB weight stages
    __shared__ __align__(8) unsigned long long mbar_s[2];

    int tid = threadIdx.x, wid = tid >> 5, lane = tid & 31;
    unsigned mb0 = smem_u32(&mbar_s[0]);
    unsigned mb1 = smem_u32(&mbar_s[1]);

    if (tid == 0) { mbar_init(mb0, 1); mbar_init(mb1, 1); }

    // token tile (plain loads)
    for (int idx = tid; idx < TB * 192; idx += 256) {
        int row = idx / 192, col = idx % 192;
        float4 v = make_float4(0.f, 0.f, 0.f, 0.f);
        if (row < n) {
            int s = g_sel[e * S_ + base + row] >> 2;
            v = *(const float4*)(g_t + (size_t)s * H_ + col * 4);
        }
        ((float4*)tile)[idx] = v;
    }

    int r0b = blockIdx.x * 32;
    const float* wbase = w1 + ((size_t)e * 2 * I_ + r0b) * H_;

    __syncthreads();    // mbarrier init + tile visible to all

    if (tid == 0) {
        mbar_expect_tx(mb0, 16384);
        issue_chunk_bulk(wbuf[0], wbase, 0, mb0);
        mbar_expect_tx(mb1, 16384);
        issue_chunk_bulk(wbuf[1], wbase, 1, mb1);
    }

    float acc[4][4];
#pragma unroll
    for (int r = 0; r < 4; r++)
#pragma unroll
        for (int i = 0; i < 4; i++) acc[r][i] = 0.f;

#pragma unroll
    for (int c = 0; c < NCH; c++) {
        unsigned mb = (c & 1) ? mb1 : mb0;
        mbar_wait(mb, (c >> 1) & 1);
        chunk_fma(wbuf[c & 1], tile, c, wid, lane, acc);
        if (c + 2 < NCH) {
            __syncthreads();   // all warps done reading wbuf[c&1]
            if (tid == 0) {
                mbar_expect_tx(mb, 16384);
                issue_chunk_bulk(wbuf[c & 1], wbase, c + 2, mb);
            }
        }
    }

    float d0 = reduce4(acc[0][0], acc[0][1], acc[0][2], acc[0][3], lane);
    float d1 = reduce4(acc[1][0], acc[1][1], acc[1][2], acc[1][3], lane);
    float d2 = reduce4(acc[2][0], acc[2][1], acc[2][2], acc[2][3], lane);
    float d3 = reduce4(acc[3][0], acc[3][1], acc[3][2], acc[3][3], lane);

    if (lane < n) {
        int sel = g_sel[e * S_ + base + lane];
        int r0 = r0b + wid * 4;
        int c0 = r0 >> 1;
        const float* bp = b1 + e * 2 * I_ + r0;
        float hg = fminf(d0 + bp[0], LIMIT_);
        float hl = fminf(fmaxf(d1 + bp[1], -LIMIT_), LIMIT_);
        float sig = 1.f / (1.f + __expf(-ALPHA_ * hg));
        g_act[sel * I_ + c0] = hg * sig * (hl + 1.f);

        float hg2 = fminf(d2 + bp[2], LIMIT_);
        float hl2 = fminf(fmaxf(d3 + bp[3], -LIMIT_), LIMIT_);
        float sig2 = 1.f / (1.f + __expf(-ALPHA_ * hg2));
        g_act[sel * I_ + c0 + 1] = hg2 * sig2 * (hl2 + 1.f);
    }
}

// ---------------------------------------------------------------------------
// Kernel 4: expert MLP-2 (32 w2 rows/block), bulk-copy 2-stage pipeline,
//           weighted accumulation into out.
// grid (H_/32, MAXW), 256 threads
// ---------------------------------------------------------------------------
__global__ void __launch_bounds__(256, 4) k_mlp2(
    const float* __restrict__ w2, const float* __restrict__ b2,
    float* __restrict__ out)
{
    int widx = blockIdx.y;
    if (widx >= g_nw) return;
    int e    = g_work[widx * 3 + 0];
    int base = g_work[widx * 3 + 1];
    int n    = g_work[widx * 3 + 2];

    __shared__ float tile[TB * I_];               // 12 KB act tile
    __shared__ float wbuf[2][32 * 128];           // 2 x 16 KB weight stages
    __shared__ __align__(8) unsigned long long mbar_s[2];

    int tid = threadIdx.x, wid = tid >> 5, lane = tid & 31;
    unsigned mb0 = smem_u32(&mbar_s[0]);
    unsigned mb1 = smem_u32(&mbar_s[1]);

    if (tid == 0) { mbar_init(mb0, 1); mbar_init(mb1, 1); }

    for (int idx = tid; idx < TB * 192; idx += 256) {
        int row = idx / 192, col = idx % 192;
        float4 v = make_float4(0.f, 0.f, 0.f, 0.f);
        if (row < n) {
            int sel = g_sel[e * S_ + base + row];
            v = *(const float4*)(g_act + (size_t)sel * I_ + col * 4);
        }
        ((float4*)tile)[idx] = v;
    }

    int c0b = blockIdx.x * 32;
    const float* wbase = w2 + ((size_t)e * H_ + c0b) * I_;

    __syncthreads();

    if (tid == 0) {
        mbar_expect_tx(mb0, 16384);
        issue_chunk_bulk(wbuf[0], wbase, 0, mb0);
        mbar_expect_tx(mb1, 16384);
        issue_chunk_bulk(wbuf[1], wbase, 1, mb1);
    }

    float acc[4][4];
#pragma unroll
    for (int r = 0; r < 4; r++)
#pragma unroll
        for (int i = 0; i < 4; i++) acc[r][i] = 0.f;

#pragma unroll
    for (int c = 0; c < NCH; c++) {
        unsigned mb = (c & 1) ? mb1 : mb0;
        mbar_wait(mb, (c >> 1) & 1);
        chunk_fma(wbuf[c & 1], tile, c, wid, lane, acc);
        if (c + 2 < NCH) {
            __syncthreads();
            if (tid == 0) {
                mbar_expect_tx(mb, 16384);
                issue_chunk_bulk(wbuf[c & 1], wbase, c + 2, mb);
            }
        }
    }

    float d0 = reduce4(acc[0][0], acc[0][1], acc[0][2], acc[0][3], lane);
    float d1 = reduce4(acc[1][0], acc[1][1], acc[1][2], acc[1][3], lane);
    float d2 = reduce4(acc[2][0], acc[2][1], acc[2][2], acc[2][3], lane);
    float d3 = reduce4(acc[3][0], acc[3][1], acc[3][2], acc[3][3], lane);

    if (lane < n) {
        int sel = g_sel[e * S_ + base + lane];
        int s = sel >> 2;
        float w = g_wts[sel];
        int c0 = c0b + wid * 4;
        const float* bp = b2 + e * H_ + c0;
        float* op = out + s * H_ + c0;
        atomicAdd(op + 0, w * (d0 + bp[0]));
        atomicAdd(op + 1, w * (d1 + bp[1]));
        atomicAdd(op + 2, w * (d2 + bp[2]));
        atomicAdd(op + 3, w * (d3 + bp[3]));
    }
}

// ---------------------------------------------------------------------------
extern "C" void kernel_launch(void* const* d_in, const int* in_sizes, int n_in,
                              void* d_out, int out_size)
{
    const float* x  = (const float*)d_in[0];
    const float* ns = (const float*)d_in[1];
    const float* gw = (const float*)d_in[2];
    const float* gb = (const float*)d_in[3];
    const float* w1 = (const float*)d_in[4];
    const float* b1 = (const float*)d_in[5];
    const float* w2 = (const float*)d_in[6];
    const float* b2 = (const float*)d_in[7];
    float* out = (float*)d_out;

    k_norm_router<<<S_, 256>>>(x, ns, gw, gb, out);
    k_build<<<1, 32>>>();
    dim3 g1(2 * I_ / 32, MAXW);   // (48, 64)
    k_mlp1<<<g1, 256>>>(w1, b1);
    dim3 g2(H_ / 32, MAXW);       // (24, 64)
    k_mlp2<<<g2, 256>>>(w2, b2, out);
}

// round 11
// speedup vs baseline: 1.3084x; 1.3084x over previous
#include <cuda_runtime.h>
#include <math.h>

#define S_ 32
#define H_ 768
#define I_ 768
#define E_ 32
#define TOPK_ 4
#define LIMIT_ 7.0f
#define ALPHA_ 1.702f
#define EPS_ 1e-5f

#define TB 4           // tokens per work chunk
#define MAXW 64        // max work chunks
#define NIT 12         // pipeline items per warp (2 rows x 128 cols each)
#define NST 5          // pipeline stages

// Scratch (device globals: allocation-free)
__device__ float g_t[S_ * H_];           // rmsnormed tokens
__device__ int   g_idx[S_ * TOPK_];      // top-k expert ids
__device__ float g_wts[S_ * TOPK_];      // softmax weights
__device__ int   g_cnt[E_];              // tokens per expert
__device__ int   g_sel[E_ * S_];         // sel = s*4+k per expert slot
__device__ float g_act[S_ * TOPK_ * I_]; // post-SwiGLU activations
__device__ int   g_work[MAXW * 3];       // (expert, base, len)
__device__ int   g_nw;

// ---- cp.async helpers ------------------------------------------------------
__device__ __forceinline__ void cp16(void* smem, const void* gmem)
{
    unsigned s = (unsigned)__cvta_generic_to_shared(smem);
    asm volatile("cp.async.cg.shared.global [%0], [%1], 16;" :: "r"(s), "l"(gmem));
}
__device__ __forceinline__ void cp_commit()
{
    asm volatile("cp.async.commit_group;");
}
template<int N>
__device__ __forceinline__ void cp_wait()
{
    asm volatile("cp.async.wait_group %0;" :: "n"(N));
}

// Packed reduction: 4 per-thread partials -> lane L (L<4) holds full sum of a[L].
__device__ __forceinline__ float reduce4(float a0, float a1, float a2, float a3, int lane)
{
    float w0 = (lane & 1) ? a1 : a0;
    float o0 = (lane & 1) ? a0 : a1;
    float b0 = w0 + __shfl_xor_sync(0xffffffffu, o0, 1);
    float w1 = (lane & 1) ? a3 : a2;
    float o1 = (lane & 1) ? a2 : a3;
    float b1 = w1 + __shfl_xor_sync(0xffffffffu, o1, 1);
    float w2 = (lane & 2) ? b1 : b0;
    float o2 = (lane & 2) ? b0 : b1;
    float c  = w2 + __shfl_xor_sync(0xffffffffu, o2, 2);
    c += __shfl_xor_sync(0xffffffffu, c, 4);
    c += __shfl_xor_sync(0xffffffffu, c, 8);
    c += __shfl_xor_sync(0xffffffffu, c, 16);
    return c;
}

// issue item (2 rows x 128 cols = 1 KB): item -> colchunk c=item>>1, rowpair p=item&1
__device__ __forceinline__ void issue_item(
    float4* buf, const float* wrow, int item, int lane)
{
    const float* src = wrow + (size_t)(2 * (item & 1)) * H_ + (item >> 1) * 128 + lane * 4;
    cp16(buf + lane, src);
    cp16(buf + 32 + lane, src + H_);
    cp_commit();
}

// compute one item: 2 rows x 4 tokens
__device__ __forceinline__ void item_fma(
    const float4* buf, const float* tile, int item, int lane, float acc[4][4])
{
    const float4* ts = (const float4*)tile + (item >> 1) * 32 + lane;
    float4 w0 = buf[lane], w1 = buf[32 + lane];
    float4 t0 = ts[0], t1 = ts[192], t2 = ts[384], t3 = ts[576];
    int p = 2 * (item & 1);
#define FMA4(r, wv, i, tv) \
    acc[r][i] += wv.x * tv.x + wv.y * tv.y + wv.z * tv.z + wv.w * tv.w;
    FMA4(p + 0, w0, 0, t0) FMA4(p + 0, w0, 1, t1) FMA4(p + 0, w0, 2, t2) FMA4(p + 0, w0, 3, t3)
    FMA4(p + 1, w1, 0, t0) FMA4(p + 1, w1, 1, t1) FMA4(p + 1, w1, 2, t2) FMA4(p + 1, w1, 3, t3)
#undef FMA4
}

// staged wait with decreasing allowance near the tail (12 items, 5 stages)
__device__ __forceinline__ void pipe_wait(int i)
{
    if (i < NIT - 4)      cp_wait<4>();
    else if (i == NIT - 4) cp_wait<3>();
    else if (i == NIT - 3) cp_wait<2>();
    else if (i == NIT - 2) cp_wait<1>();
    else                   cp_wait<0>();
}

// ---------------------------------------------------------------------------
// Kernel 1: RMSNorm + router (logits, top-4, softmax) + residual init
// ---------------------------------------------------------------------------
__global__ void __launch_bounds__(256) k_norm_router(
    const float* __restrict__ x, const float* __restrict__ nscale,
    const float* __restrict__ gw, const float* __restrict__ gb,
    float* __restrict__ out)
{
    int s   = blockIdx.x;
    int tid = threadIdx.x;
    int lane = tid & 31, wid = tid >> 5;

    __shared__ float sh_t[H_];
    __shared__ float red[8];
    __shared__ float logits[E_];

    float v0[3];
    float ss = 0.f;
#pragma unroll
    for (int q = 0; q < 3; q++) {
        float v = x[s * H_ + tid + 256 * q];
        v0[q] = v;
        ss += v * v;
    }
#pragma unroll
    for (int o = 16; o; o >>= 1) ss += __shfl_xor_sync(0xffffffffu, ss, o);
    if (lane == 0) red[wid] = ss;
    __syncthreads();
    if (tid < 8) {
        float r = red[tid];
#pragma unroll
        for (int o = 4; o; o >>= 1) r += __shfl_xor_sync(0xffu, r, o);
        if (tid == 0) red[0] = r;
    }
    __syncthreads();
    float rms = rsqrtf(red[0] / (float)H_ + EPS_);

#pragma unroll
    for (int q = 0; q < 3; q++) {
        int j = tid + 256 * q;
        float t = v0[q] * rms * nscale[j];
        sh_t[j] = t;
        g_t[s * H_ + j] = t;
        out[s * H_ + j] = v0[q];   // residual init out = x
    }
    __syncthreads();

#pragma unroll
    for (int e4 = 0; e4 < 4; e4++) {
        int e = wid * 4 + e4;
        float acc = 0.f;
        for (int j = lane; j < H_; j += 32) acc += sh_t[j] * gw[e * H_ + j];
#pragma unroll
        for (int o = 16; o; o >>= 1) acc += __shfl_xor_sync(0xffffffffu, acc, o);
        if (lane == 0) logits[e] = acc + gb[e];
    }
    __syncthreads();

    if (tid == 0) {
        float l[E_];
#pragma unroll
        for (int e = 0; e < E_; e++) l[e] = logits[e];
        float vals[TOPK_];
        int   ids[TOPK_];
#pragma unroll
        for (int k = 0; k < TOPK_; k++) {
            float m = -1e30f; int mi = 0;
            for (int e = 0; e < E_; e++) {
                if (l[e] > m) { m = l[e]; mi = e; }
            }
            vals[k] = m; ids[k] = mi; l[mi] = -1e30f;
        }
        float mx = vals[0], sum = 0.f, w[TOPK_];
#pragma unroll
        for (int k = 0; k < TOPK_; k++) { w[k] = __expf(vals[k] - mx); sum += w[k]; }
        float inv = 1.f / sum;
#pragma unroll
        for (int k = 0; k < TOPK_; k++) {
            g_idx[s * TOPK_ + k] = ids[k];
            g_wts[s * TOPK_ + k] = w[k] * inv;
        }
    }
}

// ---------------------------------------------------------------------------
// Kernel 2: build per-expert lists + work chunks (parallel, deterministic)
// one block, 128 threads
// ---------------------------------------------------------------------------
__global__ void k_build()
{
    __shared__ int sidx[S_ * TOPK_];
    __shared__ int scnt[E_];
    int tid = threadIdx.x;

    sidx[tid] = g_idx[tid];
    if (tid < E_) scnt[tid] = 0;
    __syncthreads();

    int e = sidx[tid];
    int pos = 0;
    for (int j = 0; j < S_ * TOPK_; j++)
        if (j < tid && sidx[j] == e) pos++;
    g_sel[e * S_ + pos] = tid;
    atomicAdd(&scnt[e], 1);
    __syncthreads();

    if (tid < E_) g_cnt[tid] = scnt[tid];
    if (tid == 0) {
        int w = 0;
        for (int ee = 0; ee < E_; ee++) {
            int n = scnt[ee];
            for (int base = 0; base < n; base += TB) {
                int len = n - base; if (len > TB) len = TB;
                g_work[w * 3 + 0] = ee;
                g_work[w * 3 + 1] = base;
                g_work[w * 3 + 2] = len;
                w++;
            }
        }
        g_nw = w;
    }
}

// ---------------------------------------------------------------------------
// Kernel 3: expert MLP-1 (32 w1 rows/block), warp-private 5-stage 1KB pipeline,
//           async token tile, SwiGLU fused in registers.
// grid (2I_/32, MAXW), 256 threads
// ---------------------------------------------------------------------------
__global__ void __launch_bounds__(256, 4) k_mlp1(
    const float* __restrict__ w1, const float* __restrict__ b1)
{
    int widx = blockIdx.y;
    if (widx >= g_nw) return;
    int e    = g_work[widx * 3 + 0];
    int base = g_work[widx * 3 + 1];
    int n    = g_work[widx * 3 + 2];

    __shared__ float tile[TB * H_];          // 12 KB token tile
    __shared__ float4 wbuf[8][NST][64];      // per-warp 5-stage x 1 KB = 40 KB

    int tid = threadIdx.x, wid = tid >> 5, lane = tid & 31;

    // group 0: token tile via cp.async (pad rows via plain STS zeros)
    for (int idx = tid; idx < TB * 192; idx += 256) {
        int row = idx / 192, col = idx % 192;
        if (row < n) {
            int s = g_sel[e * S_ + base + row] >> 2;
            cp16((float4*)tile + idx, g_t + (size_t)s * H_ + col * 4);
        } else {
            ((float4*)tile)[idx] = make_float4(0.f, 0.f, 0.f, 0.f);
        }
    }
    cp_commit();

    int r0 = blockIdx.x * 32 + wid * 4;
    const float* wrow = w1 + ((size_t)e * 2 * I_ + r0) * H_;

#pragma unroll
    for (int k = 0; k < NST; k++) issue_item(wbuf[wid][k], wrow, k, lane);

    float acc[4][4];
#pragma unroll
    for (int r = 0; r < 4; r++)
#pragma unroll
        for (int i = 0; i < 4; i++) acc[r][i] = 0.f;

#pragma unroll
    for (int i = 0; i < NIT; i++) {
        pipe_wait(i);
        if (i == 0) __syncthreads();   // all threads' tile groups complete
        item_fma(wbuf[wid][i % NST], tile, i, lane, acc);
        if (i + NST < NIT) issue_item(wbuf[wid][i % NST], wrow, i + NST, lane);
    }

    float d0 = reduce4(acc[0][0], acc[0][1], acc[0][2], acc[0][3], lane);
    float d1 = reduce4(acc[1][0], acc[1][1], acc[1][2], acc[1][3], lane);
    float d2 = reduce4(acc[2][0], acc[2][1], acc[2][2], acc[2][3], lane);
    float d3 = reduce4(acc[3][0], acc[3][1], acc[3][2], acc[3][3], lane);

    if (lane < n) {
        int sel = g_sel[e * S_ + base + lane];
        int c0 = r0 >> 1;
        const float* bp = b1 + e * 2 * I_ + r0;
        float hg = fminf(d0 + bp[0], LIMIT_);
        float hl = fminf(fmaxf(d1 + bp[1], -LIMIT_), LIMIT_);
        float sig = 1.f / (1.f + __expf(-ALPHA_ * hg));
        g_act[sel * I_ + c0] = hg * sig * (hl + 1.f);

        float hg2 = fminf(d2 + bp[2], LIMIT_);
        float hl2 = fminf(fmaxf(d3 + bp[3], -LIMIT_), LIMIT_);
        float sig2 = 1.f / (1.f + __expf(-ALPHA_ * hg2));
        g_act[sel * I_ + c0 + 1] = hg2 * sig2 * (hl2 + 1.f);
    }
}

// ---------------------------------------------------------------------------
// Kernel 4: expert MLP-2 (32 w2 rows/block), warp-private 5-stage 1KB pipeline,
//           async act tile, weighted accumulation into out.
// grid (H_/32, MAXW), 256 threads
// ---------------------------------------------------------------------------
__global__ void __launch_bounds__(256, 4) k_mlp2(
    const float* __restrict__ w2, const float* __restrict__ b2,
    float* __restrict__ out)
{
    int widx = blockIdx.y;
    if (widx >= g_nw) return;
    int e    = g_work[widx * 3 + 0];
    int base = g_work[widx * 3 + 1];
    int n    = g_work[widx * 3 + 2];

    __shared__ float tile[TB * I_];          // 12 KB act tile
    __shared__ float4 wbuf[8][NST][64];      // per-warp 5-stage x 1 KB = 40 KB

    int tid = threadIdx.x, wid = tid >> 5, lane = tid & 31;

    for (int idx = tid; idx < TB * 192; idx += 256) {
        int row = idx / 192, col = idx % 192;
        if (row < n) {
            int sel = g_sel[e * S_ + base + row];
            cp16((float4*)tile + idx, g_act + (size_t)sel * I_ + col * 4);
        } else {
            ((float4*)tile)[idx] = make_float4(0.f, 0.f, 0.f, 0.f);
        }
    }
    cp_commit();

    int c0 = blockIdx.x * 32 + wid * 4;
    const float* wrow = w2 + ((size_t)e * H_ + c0) * I_;

#pragma unroll
    for (int k = 0; k < NST; k++) issue_item(wbuf[wid][k], wrow, k, lane);

    float acc[4][4];
#pragma unroll
    for (int r = 0; r < 4; r++)
#pragma unroll
        for (int i = 0; i < 4; i++) acc[r][i] = 0.f;

#pragma unroll
    for (int i = 0; i < NIT; i++) {
        pipe_wait(i);
        if (i == 0) __syncthreads();
        item_fma(wbuf[wid][i % NST], tile, i, lane, acc);
        if (i + NST < NIT) issue_item(wbuf[wid][i % NST], wrow, i + NST, lane);
    }

    float d0 = reduce4(acc[0][0], acc[0][1], acc[0][2], acc[0][3], lane);
    float d1 = reduce4(acc[1][0], acc[1][1], acc[1][2], acc[1][3], lane);
    float d2 = reduce4(acc[2][0], acc[2][1], acc[2][2], acc[2][3], lane);
    float d3 = reduce4(acc[3][0], acc[3][1], acc[3][2], acc[3][3], lane);

    if (lane < n) {
        int sel = g_sel[e * S_ + base + lane];
        int s = sel >> 2;
        float w = g_wts[sel];
        const float* bp = b2 + e * H_ + c0;
        float* op = out + s * H_ + c0;
        atomicAdd(op + 0, w * (d0 + bp[0]));
        atomicAdd(op + 1, w * (d1 + bp[1]));
        atomicAdd(op + 2, w * (d2 + bp[2]));
        atomicAdd(op + 3, w * (d3 + bp[3]));
    }
}

// ---------------------------------------------------------------------------
extern "C" void kernel_launch(void* const* d_in, const int* in_sizes, int n_in,
                              void* d_out, int out_size)
{
    const float* x  = (const float*)d_in[0];
    const float* ns = (const float*)d_in[1];
    const float* gw = (const float*)d_in[2];
    const float* gb = (const float*)d_in[3];
    const float* w1 = (const float*)d_in[4];
    const float* b1 = (const float*)d_in[5];
    const float* w2 = (const float*)d_in[6];
    const float* b2 = (const float*)d_in[7];
    float* out = (float*)d_out;

    k_norm_router<<<S_, 256>>>(x, ns, gw, gb, out);
    k_build<<<1, 128>>>();
    dim3 g1(2 * I_ / 32, MAXW);   // (48, 64)
    k_mlp1<<<g1, 256>>>(w1, b1);
    dim3 g2(H_ / 32, MAXW);       // (24, 64)
    k_mlp2<<<g2, 256>>>(w2, b2, out);
}

// round 12
// speedup vs baseline: 1.3945x; 1.0658x over previous
#include <cuda_runtime.h>
#include <math.h>

#define S_ 32
#define H_ 768
#define I_ 768
#define E_ 32
#define TOPK_ 4
#define LIMIT_ 7.0f
#define ALPHA_ 1.702f
#define EPS_ 1e-5f

#define TB 4           // tokens per work chunk
#define MAXW 64        // max work chunks
#define NCH 6          // column chunks (768/128)

// Scratch (device globals: allocation-free)
__device__ float g_t[S_ * H_];           // rmsnormed tokens
__device__ int   g_idx[S_ * TOPK_];      // top-k expert ids
__device__ float g_wts[S_ * TOPK_];      // softmax weights
__device__ int   g_cnt[E_];              // tokens per expert
__device__ int   g_sel[E_ * S_];         // sel = s*4+k per expert slot
__device__ float g_act[S_ * TOPK_ * I_]; // post-SwiGLU activations
__device__ int   g_work[MAXW * 3];       // (expert, base, len)
__device__ int   g_nw;

// ---- cp.async helpers ------------------------------------------------------
__device__ __forceinline__ void cp16(void* smem, const void* gmem)
{
    unsigned s = (unsigned)__cvta_generic_to_shared(smem);
    asm volatile("cp.async.cg.shared.global [%0], [%1], 16;" :: "r"(s), "l"(gmem));
}
__device__ __forceinline__ void cp_commit()
{
    asm volatile("cp.async.commit_group;");
}
template<int N>
__device__ __forceinline__ void cp_wait()
{
    asm volatile("cp.async.wait_group %0;" :: "n"(N));
}

// Packed reduction: 4 per-thread partials -> lane L (L<4) holds full sum of a[L].
__device__ __forceinline__ float reduce4(float a0, float a1, float a2, float a3, int lane)
{
    float w0 = (lane & 1) ? a1 : a0;
    float o0 = (lane & 1) ? a0 : a1;
    float b0 = w0 + __shfl_xor_sync(0xffffffffu, o0, 1);
    float w1 = (lane & 1) ? a3 : a2;
    float o1 = (lane & 1) ? a2 : a3;
    float b1 = w1 + __shfl_xor_sync(0xffffffffu, o1, 1);
    float w2 = (lane & 2) ? b1 : b0;
    float o2 = (lane & 2) ? b0 : b1;
    float c  = w2 + __shfl_xor_sync(0xffffffffu, o2, 2);
    c += __shfl_xor_sync(0xffffffffu, c, 4);
    c += __shfl_xor_sync(0xffffffffu, c, 8);
    c += __shfl_xor_sync(0xffffffffu, c, 16);
    return c;
}

// issue one 4-row x 128-col chunk (2 KB) into this warp's stage buffer.
__device__ __forceinline__ void issue_chunk(
    float4* buf, const float* wrow, int c, int lane)
{
    const float* src = wrow + c * 128 + lane * 4;
#pragma unroll
    for (int r = 0; r < 4; r++)
        cp16(buf + r * 32 + lane, src + (size_t)r * H_);
    cp_commit();
}

// compute one chunk: this warp's 4 rows x 4 tokens (tokens read ONCE)
__device__ __forceinline__ void chunk_fma(
    const float4* buf, const float* tile, int c, int lane, float acc[4][4])
{
    const float4* ts = (const float4*)tile + c * 32 + lane;
    float4 w0 = buf[lane], w1 = buf[32 + lane], w2 = buf[64 + lane], w3 = buf[96 + lane];
    float4 t0 = ts[0], t1 = ts[192], t2 = ts[384], t3 = ts[576];

#define FMA4(r, wv, i, tv) \
    acc[r][i] += wv.x * tv.x + wv.y * tv.y + wv.z * tv.z + wv.w * tv.w;
    FMA4(0, w0, 0, t0) FMA4(0, w0, 1, t1) FMA4(0, w0, 2, t2) FMA4(0, w0, 3, t3)
    FMA4(1, w1, 0, t0) FMA4(1, w1, 1, t1) FMA4(1, w1, 2, t2) FMA4(1, w1, 3, t3)
    FMA4(2, w2, 0, t0) FMA4(2, w2, 1, t1) FMA4(2, w2, 2, t2) FMA4(2, w2, 3, t3)
    FMA4(3, w3, 0, t0) FMA4(3, w3, 1, t1) FMA4(3, w3, 2, t2) FMA4(3, w3, 3, t3)
#undef FMA4
}

// ---------------------------------------------------------------------------
// Kernel 1: RMSNorm + router (logits, top-4, softmax) + residual init
// ---------------------------------------------------------------------------
__global__ void __launch_bounds__(256) k_norm_router(
    const float* __restrict__ x, const float* __restrict__ nscale,
    const float* __restrict__ gw, const float* __restrict__ gb,
    float* __restrict__ out)
{
    int s   = blockIdx.x;
    int tid = threadIdx.x;
    int lane = tid & 31, wid = tid >> 5;

    __shared__ float sh_t[H_];
    __shared__ float red[8];
    __shared__ float logits[E_];

    float v0[3];
    float ss = 0.f;
#pragma unroll
    for (int q = 0; q < 3; q++) {
        float v = x[s * H_ + tid + 256 * q];
        v0[q] = v;
        ss += v * v;
    }
#pragma unroll
    for (int o = 16; o; o >>= 1) ss += __shfl_xor_sync(0xffffffffu, ss, o);
    if (lane == 0) red[wid] = ss;
    __syncthreads();
    if (tid < 8) {
        float r = red[tid];
#pragma unroll
        for (int o = 4; o; o >>= 1) r += __shfl_xor_sync(0xffu, r, o);
        if (tid == 0) red[0] = r;
    }
    __syncthreads();
    float rms = rsqrtf(red[0] / (float)H_ + EPS_);

#pragma unroll
    for (int q = 0; q < 3; q++) {
        int j = tid + 256 * q;
        float t = v0[q] * rms * nscale[j];
        sh_t[j] = t;
        g_t[s * H_ + j] = t;
        out[s * H_ + j] = v0[q];   // residual init out = x
    }
    __syncthreads();

#pragma unroll
    for (int e4 = 0; e4 < 4; e4++) {
        int e = wid * 4 + e4;
        float acc = 0.f;
        for (int j = lane; j < H_; j += 32) acc += sh_t[j] * gw[e * H_ + j];
#pragma unroll
        for (int o = 16; o; o >>= 1) acc += __shfl_xor_sync(0xffffffffu, acc, o);
        if (lane == 0) logits[e] = acc + gb[e];
    }
    __syncthreads();

    if (tid == 0) {
        float l[E_];
#pragma unroll
        for (int e = 0; e < E_; e++) l[e] = logits[e];
        float vals[TOPK_];
        int   ids[TOPK_];
#pragma unroll
        for (int k = 0; k < TOPK_; k++) {
            float m = -1e30f; int mi = 0;
            for (int e = 0; e < E_; e++) {
                if (l[e] > m) { m = l[e]; mi = e; }
            }
            vals[k] = m; ids[k] = mi; l[mi] = -1e30f;
        }
        float mx = vals[0], sum = 0.f, w[TOPK_];
#pragma unroll
        for (int k = 0; k < TOPK_; k++) { w[k] = __expf(vals[k] - mx); sum += w[k]; }
        float inv = 1.f / sum;
#pragma unroll
        for (int k = 0; k < TOPK_; k++) {
            g_idx[s * TOPK_ + k] = ids[k];
            g_wts[s * TOPK_ + k] = w[k] * inv;
        }
    }
}

// ---------------------------------------------------------------------------
// Kernel 2: build per-expert lists + work chunks (parallel, deterministic)
// ---------------------------------------------------------------------------
__global__ void k_build()
{
    __shared__ int sidx[S_ * TOPK_];
    __shared__ int scnt[E_];
    int tid = threadIdx.x;

    sidx[tid] = g_idx[tid];
    if (tid < E_) scnt[tid] = 0;
    __syncthreads();

    int e = sidx[tid];
    int pos = 0;
    for (int j = 0; j < S_ * TOPK_; j++)
        if (j < tid && sidx[j] == e) pos++;
    g_sel[e * S_ + pos] = tid;
    atomicAdd(&scnt[e], 1);
    __syncthreads();

    if (tid < E_) g_cnt[tid] = scnt[tid];
    if (tid == 0) {
        int w = 0;
        for (int ee = 0; ee < E_; ee++) {
            int n = scnt[ee];
            for (int base = 0; base < n; base += TB) {
                int len = n - base; if (len > TB) len = TB;
                g_work[w * 3 + 0] = ee;
                g_work[w * 3 + 1] = base;
                g_work[w * 3 + 2] = len;
                w++;
            }
        }
        g_nw = w;
    }
}

// ---------------------------------------------------------------------------
// Kernel 3: expert MLP-1 (32 w1 rows/block), warp-private 2-stage 2KB chunks,
//           async token tile, SwiGLU fused in registers.
// grid (2I_/32, MAXW), 256 threads
// ---------------------------------------------------------------------------
__global__ void __launch_bounds__(256, 4) k_mlp1(
    const float* __restrict__ w1, const float* __restrict__ b1)
{
    int widx = blockIdx.y;
    if (widx >= g_nw) return;
    int e    = g_work[widx * 3 + 0];
    int base = g_work[widx * 3 + 1];
    int n    = g_work[widx * 3 + 2];

    __shared__ float tile[TB * H_];          // 12 KB token tile
    __shared__ float4 wbuf[8][2][128];       // per-warp 2-stage x 2 KB = 32 KB

    int tid = threadIdx.x, wid = tid >> 5, lane = tid & 31;

    // group A: token tile via cp.async (pad rows via plain STS zeros)
    for (int idx = tid; idx < TB * 192; idx += 256) {
        int row = idx / 192, col = idx % 192;
        if (row < n) {
            int s = g_sel[e * S_ + base + row] >> 2;
            cp16((float4*)tile + idx, g_t + (size_t)s * H_ + col * 4);
        } else {
            ((float4*)tile)[idx] = make_float4(0.f, 0.f, 0.f, 0.f);
        }
    }
    cp_commit();

    int r0 = blockIdx.x * 32 + wid * 4;
    const float* wrow = w1 + ((size_t)e * 2 * I_ + r0) * H_;

    issue_chunk(wbuf[wid][0], wrow, 0, lane);   // group B
    issue_chunk(wbuf[wid][1], wrow, 1, lane);   // group C

    float acc[4][4];
#pragma unroll
    for (int r = 0; r < 4; r++)
#pragma unroll
        for (int i = 0; i < 4; i++) acc[r][i] = 0.f;

#pragma unroll
    for (int c = 0; c < NCH; c++) {
        if (c < NCH - 1) cp_wait<1>(); else cp_wait<0>();
        if (c == 0) __syncthreads();   // tile complete for all threads
        chunk_fma(wbuf[wid][c & 1], tile, c, lane, acc);
        if (c + 2 < NCH) issue_chunk(wbuf[wid][c & 1], wrow, c + 2, lane);
    }

    float d0 = reduce4(acc[0][0], acc[0][1], acc[0][2], acc[0][3], lane);
    float d1 = reduce4(acc[1][0], acc[1][1], acc[1][2], acc[1][3], lane);
    float d2 = reduce4(acc[2][0], acc[2][1], acc[2][2], acc[2][3], lane);
    float d3 = reduce4(acc[3][0], acc[3][1], acc[3][2], acc[3][3], lane);

    if (lane < n) {
        int sel = g_sel[e * S_ + base + lane];
        int c0 = r0 >> 1;
        const float* bp = b1 + e * 2 * I_ + r0;
        float hg = fminf(d0 + bp[0], LIMIT_);
        float hl = fminf(fmaxf(d1 + bp[1], -LIMIT_), LIMIT_);
        float sig = 1.f / (1.f + __expf(-ALPHA_ * hg));
        g_act[sel * I_ + c0] = hg * sig * (hl + 1.f);

        float hg2 = fminf(d2 + bp[2], LIMIT_);
        float hl2 = fminf(fmaxf(d3 + bp[3], -LIMIT_), LIMIT_);
        float sig2 = 1.f / (1.f + __expf(-ALPHA_ * hg2));
        g_act[sel * I_ + c0 + 1] = hg2 * sig2 * (hl2 + 1.f);
    }
}

// ---------------------------------------------------------------------------
// Kernel 4: expert MLP-2 (32 w2 rows/block), warp-private 2-stage 2KB chunks,
//           async act tile, weighted accumulation into out.
// grid (H_/32, MAXW), 256 threads
// ---------------------------------------------------------------------------
__global__ void __launch_bounds__(256, 4) k_mlp2(
    const float* __restrict__ w2, const float* __restrict__ b2,
    float* __restrict__ out)
{
    int widx = blockIdx.y;
    if (widx >= g_nw) return;
    int e    = g_work[widx * 3 + 0];
    int base = g_work[widx * 3 + 1];
    int n    = g_work[widx * 3 + 2];

    __shared__ float tile[TB * I_];          // 12 KB act tile
    __shared__ float4 wbuf[8][2][128];       // per-warp 2-stage x 2 KB = 32 KB

    int tid = threadIdx.x, wid = tid >> 5, lane = tid & 31;

    for (int idx = tid; idx < TB * 192; idx += 256) {
        int row = idx / 192, col = idx % 192;
        if (row < n) {
            int sel = g_sel[e * S_ + base + row];
            cp16((float4*)tile + idx, g_act + (size_t)sel * I_ + col * 4);
        } else {
            ((float4*)tile)[idx] = make_float4(0.f, 0.f, 0.f, 0.f);
        }
    }
    cp_commit();

    int c0 = blockIdx.x * 32 + wid * 4;
    const float* wrow = w2 + ((size_t)e * H_ + c0) * I_;

    issue_chunk(wbuf[wid][0], wrow, 0, lane);
    issue_chunk(wbuf[wid][1], wrow, 1, lane);

    float acc[4][4];
#pragma unroll
    for (int r = 0; r < 4; r++)
#pragma unroll
        for (int i = 0; i < 4; i++) acc[r][i] = 0.f;

#pragma unroll
    for (int c = 0; c < NCH; c++) {
        if (c < NCH - 1) cp_wait<1>(); else cp_wait<0>();
        if (c == 0) __syncthreads();
        chunk_fma(wbuf[wid][c & 1], tile, c, lane, acc);
        if (c + 2 < NCH) issue_chunk(wbuf[wid][c & 1], wrow, c + 2, lane);
    }

    float d0 = reduce4(acc[0][0], acc[0][1], acc[0][2], acc[0][3], lane);
    float d1 = reduce4(acc[1][0], acc[1][1], acc[1][2], acc[1][3], lane);
    float d2 = reduce4(acc[2][0], acc[2][1], acc[2][2], acc[2][3], lane);
    float d3 = reduce4(acc[3][0], acc[3][1], acc[3][2], acc[3][3], lane);

    if (lane < n) {
        int sel = g_sel[e * S_ + base + lane];
        int s = sel >> 2;
        float w = g_wts[sel];
        const float* bp = b2 + e * H_ + c0;
        float* op = out + s * H_ + c0;
        atomicAdd(op + 0, w * (d0 + bp[0]));
        atomicAdd(op + 1, w * (d1 + bp[1]));
        atomicAdd(op + 2, w * (d2 + bp[2]));
        atomicAdd(op + 3, w * (d3 + bp[3]));
    }
}

// ---------------------------------------------------------------------------
extern "C" void kernel_launch(void* const* d_in, const int* in_sizes, int n_in,
                              void* d_out, int out_size)
{
    const float* x  = (const float*)d_in[0];
    const float* ns = (const float*)d_in[1];
    const float* gw = (const float*)d_in[2];
    const float* gb = (const float*)d_in[3];
    const float* w1 = (const float*)d_in[4];
    const float* b1 = (const float*)d_in[5];
    const float* w2 = (const float*)d_in[6];
    const float* b2 = (const float*)d_in[7];
    float* out = (float*)d_out;

    k_norm_router<<<S_, 256>>>(x, ns, gw, gb, out);
    k_build<<<1, 128>>>();
    dim3 g1(2 * I_ / 32, MAXW);   // (48, 64)
    k_mlp1<<<g1, 256>>>(w1, b1);
    dim3 g2(H_ / 32, MAXW);       // (24, 64)
    k_mlp2<<<g2, 256>>>(w2, b2, out);
}